// round 7
// baseline (speedup 1.0000x reference)
#include <cuda_runtime.h>

// ---------------------------------------------------------------------------
// DGLossVer2: fused gyro (SO3 chain) + gaussian-NLL scalar loss, ONE launch.
// N=128 seqs, T=16384 steps, 3 ch. One warp handles 128 consecutive steps:
//   each lane: product of its 4 steps (3 in-thread matmuls)
//   fold rounds -> 16-products at lanes %4==0, 32-products at %8==0
//   residual logs vs exp(dw16[::16]), GNLL fused (grouped logs).
// Last block performs the final reduction (threadfence pattern).
// ---------------------------------------------------------------------------

#define FULL_MASK 0xFFFFFFFFu

#define C16F  (25.0f / 391296.0f)    // W*H^2 / (128*1019*3)
#define C32F  (6.25f / 194688.0f)    // W*H^2/4 / (128*507*3)
#define CNLLF (0.5f  / 6291456.0f)   // 0.5 / (128*16384*3)

#define NBLK 2048

static __device__ float g_part[NBLK];
static __device__ unsigned int g_ticket;   // zero-init; last block resets to 0

struct Mat3 { float a[9]; };   // row-major

__device__ __forceinline__ Mat3 mat_mul(const Mat3& A, const Mat3& B) {
    Mat3 C;
#pragma unroll
    for (int i = 0; i < 3; i++)
#pragma unroll
        for (int j = 0; j < 3; j++)
            C.a[3*i+j] = A.a[3*i+0]*B.a[0+j] + A.a[3*i+1]*B.a[3+j] + A.a[3*i+2]*B.a[6+j];
    return C;
}

// C = A^T * B
__device__ __forceinline__ Mat3 mat_tmul(const Mat3& A, const Mat3& B) {
    Mat3 C;
#pragma unroll
    for (int i = 0; i < 3; i++)
#pragma unroll
        for (int j = 0; j < 3; j++)
            C.a[3*i+j] = A.a[0+i]*B.a[0+j] + A.a[3+i]*B.a[3+j] + A.a[6+i]*B.a[6+j];
    return C;
}

__device__ __forceinline__ Mat3 shfl_down_mat(const Mat3& M, int d) {
    Mat3 R;
#pragma unroll
    for (int i = 0; i < 9; i++) R.a[i] = __shfl_down_sync(FULL_MASK, M.a[i], d);
    return R;
}

__device__ __forceinline__ Mat3 rot_from(float x, float y, float z,
                                         float sin_t, float cos_t) {
    Mat3 R;
    float xy = x*y, xz = x*z, yz = y*z;
    R.a[0] = 1.0f - cos_t * (y*y + z*z);
    R.a[1] = -sin_t*z + cos_t*xy;
    R.a[2] =  sin_t*y + cos_t*xz;
    R.a[3] =  sin_t*z + cos_t*xy;
    R.a[4] = 1.0f - cos_t * (x*x + z*z);
    R.a[5] = -sin_t*x + cos_t*yz;
    R.a[6] = -sin_t*y + cos_t*xz;
    R.a[7] =  sin_t*x + cos_t*yz;
    R.a[8] = 1.0f - cos_t * (x*x + y*y);
    return R;
}

// angles <= ~0.04 rad: Taylor, error ~1e-12
__device__ __forceinline__ Mat3 so3_exp_small(float x, float y, float z) {
    float a2 = x*x + y*y + z*z;
    float sin_t = 1.0f + a2 * (-(1.0f/6.0f)  + a2 * (1.0f/120.0f));
    float cos_t = 0.5f + a2 * (-(1.0f/24.0f) + a2 * (1.0f/720.0f));
    return rot_from(x, y, z, sin_t, cos_t);
}

// full-range (dw16 samples)
__device__ __forceinline__ Mat3 so3_exp_full(float x, float y, float z) {
    float a2 = x*x + y*y + z*z;
    float sin_t, cos_t;
    if (a2 < 1e-12f) {
        sin_t = 1.0f - a2 * (1.0f/6.0f);
        cos_t = 0.5f - a2 * (1.0f/24.0f);
    } else {
        float a = sqrtf(a2);
        sin_t = __sinf(a) / a;
        cos_t = (1.0f - __cosf(a)) / a2;
    }
    return rot_from(x, y, z, sin_t, cos_t);
}

// reference clips cos; sin(acos(c)) = sqrt(1-c^2)
__device__ __forceinline__ void so3_log_vec(const Mat3& R, float r[3]) {
    float tr = R.a[0] + R.a[4] + R.a[8];
    float c = 0.5f * (tr - 1.0f);
    c = fminf(fmaxf(c, -1.0f + 1e-6f), 1.0f - 1e-6f);
    float factor = 0.5f * acosf(c) * rsqrtf((1.0f - c) * (1.0f + c));
    r[0] = factor * (R.a[7] - R.a[5]);
    r[1] = factor * (R.a[2] - R.a[6]);
    r[2] = factor * (R.a[3] - R.a[1]);
}

__device__ __forceinline__ float huber3(const float r[3]) {
    float s = 0.0f;
#pragma unroll
    for (int c = 0; c < 3; c++) {
        float x = fabsf(r[c]) * 200.0f;      // 1/HUBER
        s += (x < 1.0f) ? 0.5f * x * x : x - 0.5f;
    }
    return s;
}

__device__ __forceinline__ void load12(const float* __restrict__ p, int base, float v[12]) {
    const float4* p4 = reinterpret_cast<const float4*>(p + base);
    *reinterpret_cast<float4*>(&v[0]) = p4[0];
    *reinterpret_cast<float4*>(&v[4]) = p4[1];
    *reinterpret_cast<float4*>(&v[8]) = p4[2];
}

__global__ void __launch_bounds__(256, 5)
loss_kernel(const float* __restrict__ w_hat,
            const float* __restrict__ dw16,
            const float* __restrict__ w_gt,
            const float* __restrict__ w_mean,
            const float* __restrict__ w_std,
            float* __restrict__ out) {
    const int lane = threadIdx.x & 31;
    const int w = blockIdx.x * 8 + (threadIdx.x >> 5);   // 16384 warps total
    const int n  = w >> 7;                               // 128 warps per sequence
    const int jw = w & 127;
    const int t0 = (n << 14) + (jw << 7) + (lane << 2);  // first of 4 steps
    const int base = t0 * 3;                             // 48B-aligned float offset

    // ---- loads (3x LDG.128 per array) ----
    float h[12], g[12], m[12], s[12];
    load12(w_hat,  base, h);
    load12(w_gt,   base, g);
    load12(w_mean, base, m);
    load12(w_std,  base, s);

    // ---- gaussian NLL over 4 steps; logs grouped by 4 ----
    float accf;
    {
        float gn = 0.0f;
#pragma unroll
        for (int c = 0; c < 3; c++) {
            float v0 = fmaxf(s[4*c+0]*s[4*c+0], 1e-6f);
            float v1 = fmaxf(s[4*c+1]*s[4*c+1], 1e-6f);
            float v2 = fmaxf(s[4*c+2]*s[4*c+2], 1e-6f);
            float v3 = fmaxf(s[4*c+3]*s[4*c+3], 1e-6f);
            float d0 = g[4*c+0] - h[4*c+0] - m[4*c+0];
            float d1 = g[4*c+1] - h[4*c+1] - m[4*c+1];
            float d2 = g[4*c+2] - h[4*c+2] - m[4*c+2];
            float d3 = g[4*c+3] - h[4*c+3] - m[4*c+3];
            gn += __fdividef(d0*d0, v0) + __fdividef(d1*d1, v1)
                + __fdividef(d2*d2, v2) + __fdividef(d3*d3, v3);
            gn += __logf(v0 * v1 * v2 * v3);   // grouped log, min 1e-24 > FLT_MIN
        }
        accf = gn * CNLLF;
    }

    // ---- gyro chain: product of this thread's 4 steps ----
    Mat3 M = so3_exp_small(0.005f*h[0], 0.005f*h[1], 0.005f*h[2]);
#pragma unroll
    for (int st = 1; st < 4; st++) {
        Mat3 R = so3_exp_small(0.005f*h[3*st], 0.005f*h[3*st+1], 0.005f*h[3*st+2]);
        M = mat_mul(M, R);
    }

    // ---- warp folds: 8-prod, 16-prod (lanes %4==0), 32-prod (lanes %8==0) ----
    {
        Mat3 T = shfl_down_mat(M, 1); M = mat_mul(M, T);
    }
    {
        Mat3 T = shfl_down_mat(M, 2); M = mat_mul(M, T);   // 16-product
    }
    Mat3 T4 = shfl_down_mat(M, 4);
    Mat3 Q32 = mat_mul(M, T4);                             // 32-product (%8==0)

    // ---- P = exp(dw16) at sample lanes (t0 % 16 == 0 <=> lane%4==0) ----
    const bool samp = ((lane & 3) == 0);
    float dx = 0.0f, dy = 0.0f, dz = 0.0f;
    if (samp) { dx = dw16[base]; dy = dw16[base+1]; dz = dw16[base+2]; }
    Mat3 P = so3_exp_full(dx, dy, dz);                     // identity on non-sample lanes
    Mat3 Pn = shfl_down_mat(P, 4);

    // ---- 16-level residual (8 per warp) ----
    if (samp) {
        int il = (jw << 3) + (lane >> 2);
        if (il >= 5) {
            Mat3 Mr = mat_tmul(M, P);                      // Q16^T P
            float r[3]; so3_log_vec(Mr, r);
            accf += huber3(r) * C16F;
        }
    }
    // ---- 32-level residual (4 per warp) ----
    if ((lane & 7) == 0) {
        int i32 = (jw << 2) + (lane >> 3);
        if (i32 >= 5) {
            Mat3 P2 = mat_mul(P, Pn);
            Mat3 Mr = mat_tmul(Q32, P2);
            float r[3]; so3_log_vec(Mr, r);
            accf += huber3(r) * C32F;
        }
    }

    // ---- block reduce ----
#pragma unroll
    for (int d = 16; d > 0; d >>= 1)
        accf += __shfl_down_sync(FULL_MASK, accf, d);

    __shared__ float ssum[8];
    __shared__ bool s_last;
    if (lane == 0) ssum[threadIdx.x >> 5] = accf;
    __syncthreads();
    if (threadIdx.x == 0) {
        float t = 0.0f;
#pragma unroll
        for (int i = 0; i < 8; i++) t += ssum[i];
        g_part[blockIdx.x] = t;
        __threadfence();
        unsigned int tk = atomicAdd(&g_ticket, 1u);
        s_last = (tk == NBLK - 1u);
    }
    __syncthreads();

    // ---- last block: final reduction + output + ticket reset ----
    if (s_last) {
        double v = 0.0;
#pragma unroll
        for (int i = 0; i < NBLK / 256; i++)
            v += (double)g_part[threadIdx.x + 256 * i];
#pragma unroll
        for (int d = 16; d > 0; d >>= 1)
            v += __shfl_down_sync(FULL_MASK, v, d);
        __shared__ double sd[8];
        if (lane == 0) sd[threadIdx.x >> 5] = v;
        __syncthreads();
        if (threadIdx.x == 0) {
            double t = 0.0;
#pragma unroll
            for (int i = 0; i < 8; i++) t += sd[i];
            out[0] = (float)t;
            g_ticket = 0;          // reset for next graph replay
        }
    }
}

extern "C" void kernel_launch(void* const* d_in, const int* in_sizes, int n_in,
                              void* d_out, int out_size) {
    const float* w_hat  = (const float*)d_in[0];
    const float* dw16   = (const float*)d_in[1];
    const float* w_gt   = (const float*)d_in[2];
    const float* w_mean = (const float*)d_in[3];
    const float* w_std  = (const float*)d_in[4];
    float* out = (float*)d_out;

    // 16384 warps -> 2048 blocks x 256 threads, single launch
    loss_kernel<<<NBLK, 256>>>(w_hat, dw16, w_gt, w_mean, w_std, out);
}

// round 8
// speedup vs baseline: 1.0755x; 1.0755x over previous
#include <cuda_runtime.h>

// ---------------------------------------------------------------------------
// DGLossVer2: fused gyro (SO3 chain, QUATERNION form) + gaussian-NLL, ONE launch.
// N=128 seqs, T=16384 steps, 3 ch. One warp handles 256 consecutive steps:
//   each lane: quat product of its 8 steps (7 in-thread qmuls)
//   2 shfl fold rounds -> 16-products at even lanes, 32-products at %4==0
//   residuals: log(conj(qQ)*qP) vs exp(dw16[::16]); GNLL fused (grouped logs).
// Log identity: for unit q, tr(R)=4w^2-1 => c=2w^2-1 (same clip as reference),
// vee(R-R^T)=4*w*qv => r = 2*acos(c)*rsqrt(1-c^2)*w*qv.  (+/-q invariant.)
// Last block performs the final reduction (threadfence pattern).
// ---------------------------------------------------------------------------

#define FULL_MASK 0xFFFFFFFFu

#define C16F  (25.0f / 391296.0f)    // W*H^2 / (128*1019*3)
#define C32F  (6.25f / 194688.0f)    // W*H^2/4 / (128*507*3)
#define CNLLF (0.5f  / 6291456.0f)   // 0.5 / (128*16384*3)

#define NBLK 1024

static __device__ float g_part[NBLK];
static __device__ unsigned int g_ticket;   // zero-init; last block resets to 0

struct Quat { float w, x, y, z; };

// Hamilton product: R(a*b) = R(a)*R(b)
__device__ __forceinline__ Quat qmul(const Quat& a, const Quat& b) {
    Quat c;
    c.w = a.w*b.w - a.x*b.x - a.y*b.y - a.z*b.z;
    c.x = a.w*b.x + a.x*b.w + a.y*b.z - a.z*b.y;
    c.y = a.w*b.y - a.x*b.z + a.y*b.w + a.z*b.x;
    c.z = a.w*b.z + a.x*b.y - a.y*b.x + a.z*b.w;
    return c;
}

// conj(a) * b  == A^T B in rotation space
__device__ __forceinline__ Quat qcmul(const Quat& a, const Quat& b) {
    Quat c;
    c.w = a.w*b.w + a.x*b.x + a.y*b.y + a.z*b.z;
    c.x = a.w*b.x - a.x*b.w - a.y*b.z + a.z*b.y;
    c.y = a.w*b.y + a.x*b.z - a.y*b.w - a.z*b.x;
    c.z = a.w*b.z - a.x*b.y + a.y*b.x - a.z*b.w;
    return c;
}

__device__ __forceinline__ Quat shfl_down_quat(const Quat& q, int d) {
    Quat r;
    r.w = __shfl_down_sync(FULL_MASK, q.w, d);
    r.x = __shfl_down_sync(FULL_MASK, q.x, d);
    r.y = __shfl_down_sync(FULL_MASK, q.y, d);
    r.z = __shfl_down_sync(FULL_MASK, q.z, d);
    return r;
}

// exp for |phi| <= ~0.04 rad: half-angle Taylor, error ~1e-12
// input already scaled: u = 0.5*DT*w_hat
__device__ __forceinline__ Quat qexp_small(float ux, float uy, float uz) {
    float a2 = ux*ux + uy*uy + uz*uz;           // |u|^2, <= ~3e-4
    float sc = 1.0f + a2 * (-(1.0f/6.0f)  + a2 * (1.0f/120.0f));  // sin|u|/|u|
    float cw = 1.0f + a2 * (-0.5f         + a2 * (1.0f/24.0f));   // cos|u|
    Quat q; q.w = cw; q.x = sc*ux; q.y = sc*uy; q.z = sc*uz;
    return q;
}

// full-range exp (dw16 samples): q = (cos(a/2), sin(a/2)/a * phi)
__device__ __forceinline__ Quat qexp_full(float x, float y, float z) {
    float a2 = x*x + y*y + z*z;
    float a  = sqrtf(a2);
    float half = 0.5f * a;
    float s = (a2 < 1e-12f) ? 0.5f : (__sinf(half) / a);
    Quat q; q.w = __cosf(half); q.x = s*x; q.y = s*y; q.z = s*z;
    return q;
}

// so3 log from quaternion, replicating reference's clipped-trace formula
__device__ __forceinline__ void qlog_vec(const Quat& q, float r[3]) {
    float c = 2.0f * q.w * q.w - 1.0f;                       // = 0.5*(tr-1)
    c = fminf(fmaxf(c, -1.0f + 1e-6f), 1.0f - 1e-6f);
    // factor_ref = ang/(2 sin ang); r = factor_ref * 4*w*qv
    float f = 2.0f * acosf(c) * rsqrtf((1.0f - c) * (1.0f + c)) * q.w;
    r[0] = f * q.x; r[1] = f * q.y; r[2] = f * q.z;
}

__device__ __forceinline__ float huber3(const float r[3]) {
    float s = 0.0f;
#pragma unroll
    for (int c = 0; c < 3; c++) {
        float x = fabsf(r[c]) * 200.0f;      // 1/HUBER
        s += (x < 1.0f) ? 0.5f * x * x : x - 0.5f;
    }
    return s;
}

__global__ void __launch_bounds__(256, 4)
loss_kernel(const float* __restrict__ w_hat,
            const float* __restrict__ dw16,
            const float* __restrict__ w_gt,
            const float* __restrict__ w_mean,
            const float* __restrict__ w_std,
            float* __restrict__ out) {
    const int lane = threadIdx.x & 31;
    const int w = blockIdx.x * 8 + (threadIdx.x >> 5);   // 8192 warps total
    const int n  = w >> 6;                               // 64 warps per sequence
    const int jw = w & 63;
    const int t0 = (n << 14) + (jw << 8) + (lane << 3);  // first of 8 steps
    const int base = t0 * 3;                             // 96B-aligned float offset

    // ---- w_hat: 6x LDG.128 (24 floats = 8 steps) ----
    float h[24];
    {
        const float4* p4 = reinterpret_cast<const float4*>(w_hat + base);
#pragma unroll
        for (int c = 0; c < 6; c++)
            *reinterpret_cast<float4*>(&h[4*c]) = p4[c];
    }

    // ---- gaussian NLL, streamed float4 chunks; logs grouped by 4 ----
    float accf;
    {
        const float4* g4 = reinterpret_cast<const float4*>(w_gt   + base);
        const float4* m4 = reinterpret_cast<const float4*>(w_mean + base);
        const float4* s4 = reinterpret_cast<const float4*>(w_std  + base);
        float gn = 0.0f;
#pragma unroll
        for (int c = 0; c < 6; c++) {
            float4 gv = g4[c], mv = m4[c], sv = s4[c];
            float v0 = fmaxf(sv.x*sv.x, 1e-6f);
            float v1 = fmaxf(sv.y*sv.y, 1e-6f);
            float v2 = fmaxf(sv.z*sv.z, 1e-6f);
            float v3 = fmaxf(sv.w*sv.w, 1e-6f);
            float d0 = gv.x - h[4*c+0] - mv.x;
            float d1 = gv.y - h[4*c+1] - mv.y;
            float d2 = gv.z - h[4*c+2] - mv.z;
            float d3 = gv.w - h[4*c+3] - mv.w;
            gn += __fdividef(d0*d0, v0) + __fdividef(d1*d1, v1)
                + __fdividef(d2*d2, v2) + __fdividef(d3*d3, v3);
            gn += __logf(v0 * v1 * v2 * v3);   // grouped log, min 1e-24 > FLT_MIN
        }
        accf = gn * CNLLF;
    }

    // ---- gyro chain: quat product of this thread's 8 steps ----
    // u = 0.5*DT*h = 0.0025*h
    Quat M = qexp_small(0.0025f*h[0], 0.0025f*h[1], 0.0025f*h[2]);
#pragma unroll
    for (int st = 1; st < 8; st++) {
        Quat R = qexp_small(0.0025f*h[3*st], 0.0025f*h[3*st+1], 0.0025f*h[3*st+2]);
        M = qmul(M, R);
    }

    // ---- warp folds: 16-prod at even lanes, 32-prod at lanes %4==0 ----
    {
        Quat T = shfl_down_quat(M, 1); M = qmul(M, T);   // 16-product
    }
    Quat T2 = shfl_down_quat(M, 2);
    Quat Q32 = qmul(M, T2);                              // 32-product (%4==0)

    // ---- P = exp(dw16) at sample lanes (t0 % 16 == 0 <=> even lane) ----
    const bool samp = ((lane & 1) == 0);
    float dx = 0.0f, dy = 0.0f, dz = 0.0f;
    if (samp) { dx = dw16[base]; dy = dw16[base+1]; dz = dw16[base+2]; }
    Quat P = qexp_full(dx, dy, dz);                      // identity on odd lanes
    Quat Pn = shfl_down_quat(P, 2);

    // ---- 16-level residual (16 per warp) ----
    if (samp) {
        int il = (jw << 4) + (lane >> 1);
        if (il >= 5) {
            Quat Mr = qcmul(M, P);                       // Q16^T P
            float r[3]; qlog_vec(Mr, r);
            accf += huber3(r) * C16F;
        }
    }
    // ---- 32-level residual (8 per warp) ----
    if ((lane & 3) == 0) {
        int i32 = (jw << 3) + (lane >> 2);
        if (i32 >= 5) {
            Quat P2 = qmul(P, Pn);
            Quat Mr = qcmul(Q32, P2);
            float r[3]; qlog_vec(Mr, r);
            accf += huber3(r) * C32F;
        }
    }

    // ---- block reduce ----
#pragma unroll
    for (int d = 16; d > 0; d >>= 1)
        accf += __shfl_down_sync(FULL_MASK, accf, d);

    __shared__ float ssum[8];
    __shared__ bool s_last;
    if (lane == 0) ssum[threadIdx.x >> 5] = accf;
    __syncthreads();
    if (threadIdx.x == 0) {
        float t = 0.0f;
#pragma unroll
        for (int i = 0; i < 8; i++) t += ssum[i];
        g_part[blockIdx.x] = t;
        __threadfence();
        unsigned int tk = atomicAdd(&g_ticket, 1u);
        s_last = (tk == NBLK - 1u);
    }
    __syncthreads();

    // ---- last block: final reduction + output + ticket reset ----
    if (s_last) {
        double v = 0.0;
#pragma unroll
        for (int i = 0; i < NBLK / 256; i++)
            v += (double)g_part[threadIdx.x + 256 * i];
#pragma unroll
        for (int d = 16; d > 0; d >>= 1)
            v += __shfl_down_sync(FULL_MASK, v, d);
        __shared__ double sd[8];
        if (lane == 0) sd[threadIdx.x >> 5] = v;
        __syncthreads();
        if (threadIdx.x == 0) {
            double t = 0.0;
#pragma unroll
            for (int i = 0; i < 8; i++) t += sd[i];
            out[0] = (float)t;
            g_ticket = 0;          // reset for next graph replay
        }
    }
}

extern "C" void kernel_launch(void* const* d_in, const int* in_sizes, int n_in,
                              void* d_out, int out_size) {
    const float* w_hat  = (const float*)d_in[0];
    const float* dw16   = (const float*)d_in[1];
    const float* w_gt   = (const float*)d_in[2];
    const float* w_mean = (const float*)d_in[3];
    const float* w_std  = (const float*)d_in[4];
    float* out = (float*)d_out;

    // 8192 warps -> 1024 blocks x 256 threads, single launch
    loss_kernel<<<NBLK, 256>>>(w_hat, dw16, w_gt, w_mean, w_std, out);
}